// round 4
// baseline (speedup 1.0000x reference)
#include <cuda_runtime.h>
#include <cuda_bf16.h>
#include <math.h>
#include <stdint.h>

// Problem constants
#define BB 2
#define SS 2048
#define DD 1024
#define HH 16
#define DQ 64

// Attention tiling
#define BM 64
#define BN 64

#define EPS_MASKED 9.357623e-14f   // exp(-30)

// ctx scratch, split bf16 hi/lo
__device__ __nv_bfloat16 g_ctx_h[BB * SS * DD];
__device__ __nv_bfloat16 g_ctx_l[BB * SS * DD];
// W split bf16 hi/lo
__device__ __nv_bfloat16 g_w_h[DD * DD];
__device__ __nv_bfloat16 g_w_l[DD * DD];

// ===========================================================================
// Helpers
// ===========================================================================
__device__ __forceinline__ uint32_t smem_u32(const void* p) {
    uint32_t a;
    asm("{ .reg .u64 t; cvta.to.shared.u64 t, %1; cvt.u32.u64 %0, t; }" : "=r"(a) : "l"(p));
    return a;
}
__device__ __forceinline__ uint32_t swz(uint32_t off) {
    return off ^ ((off >> 3) & 0x70);
}
__device__ __forceinline__ void ldsm4(uint32_t* r, uint32_t addr) {
    asm volatile("ldmatrix.sync.aligned.m8n8.x4.shared.b16 {%0,%1,%2,%3}, [%4];"
                 : "=r"(r[0]), "=r"(r[1]), "=r"(r[2]), "=r"(r[3]) : "r"(addr));
}
__device__ __forceinline__ void ldsm4t(uint32_t* r, uint32_t addr) {
    asm volatile("ldmatrix.sync.aligned.m8n8.x4.trans.shared.b16 {%0,%1,%2,%3}, [%4];"
                 : "=r"(r[0]), "=r"(r[1]), "=r"(r[2]), "=r"(r[3]) : "r"(addr));
}
__device__ __forceinline__ void mma16816(float* c, const uint32_t* a, uint32_t b0, uint32_t b1) {
    asm volatile("mma.sync.aligned.m16n8k16.row.col.f32.bf16.bf16.f32 "
                 "{%0,%1,%2,%3}, {%4,%5,%6,%7}, {%8,%9}, {%0,%1,%2,%3};"
                 : "+f"(c[0]), "+f"(c[1]), "+f"(c[2]), "+f"(c[3])
                 : "r"(a[0]), "r"(a[1]), "r"(a[2]), "r"(a[3]), "r"(b0), "r"(b1));
}
__device__ __forceinline__ void split2(float x, float y, uint32_t& hi, uint32_t& lo) {
    __nv_bfloat162 h = __floats2bfloat162_rn(x, y);
    float rx = x - __bfloat162float(h.x);
    float ry = y - __bfloat162float(h.y);
    __nv_bfloat162 l = __floats2bfloat162_rn(rx, ry);
    hi = *reinterpret_cast<uint32_t*>(&h);
    lo = *reinterpret_cast<uint32_t*>(&l);
}
__device__ __forceinline__ void split4(float4 v, uint2& hi, uint2& lo) {
    split2(v.x, v.y, hi.x, lo.x);
    split2(v.z, v.w, hi.y, lo.y);
}

// ===========================================================================
// W pre-split: f32 -> bf16 hi/lo. 262144 float4s.
// ===========================================================================
extern "C" __global__ void __launch_bounds__(256)
convert_w(const float* __restrict__ W)
{
    int i = blockIdx.x * 256 + threadIdx.x;
    float4 v = reinterpret_cast<const float4*>(W)[i];
    uint2 hi, lo;
    split4(v, hi, lo);
    reinterpret_cast<uint2*>(g_w_h)[i] = hi;
    reinterpret_cast<uint2*>(g_w_l)[i] = lo;
}

// ===========================================================================
// Smem layout for attention (bytes): 6 tiles of [64 rows][64 bf16] = 8 KB each.
// ===========================================================================
#define SM_QH 0
#define SM_QL 8192
#define SM_KH 16384
#define SM_KL 24576
#define SM_VH 32768
#define SM_VL 40960
#define SMEM_BYTES 49152

// ===========================================================================
// Flash attention via mma.sync bf16, 3-term hi/lo split.
// 128 threads (4 warps x 16 query rows). Grid (32, 16, 2).
// ===========================================================================
extern "C" __global__ void __launch_bounds__(128)
attn_mma(const float* __restrict__ Q,
         const float* __restrict__ K,
         const float* __restrict__ V)
{
    extern __shared__ char smc[];
    const uint32_t sb = smem_u32(smc);
    const int tid  = threadIdx.x;
    const int lane = tid & 31;
    const int wid  = tid >> 5;

    const int bx = blockIdx.x;
    const int qt = (bx == 0) ? 31 : (bx == 1) ? 0 : (32 - bx);
    const int h  = blockIdx.y;
    const int b  = blockIdx.z;
    const int q0 = qt * BM;

    const float* Qb = Q + ((size_t)(b * SS + q0)) * DD + h * DQ;
    const float* Kb = K + ((size_t)b * SS) * DD + h * DQ;
    const float* Vb = V + ((size_t)b * SS) * DD + h * DQ;

#pragma unroll
    for (int it = 0; it < 8; it++) {
        int idx = it * 128 + tid;
        int r = idx >> 4;
        int g = idx & 15;
        float4 q4 = *reinterpret_cast<const float4*>(Qb + (size_t)r * DD + g * 4);
        uint2 hi, lo;
        split4(q4, hi, lo);
        uint32_t off = swz((uint32_t)(r * 128 + g * 8));
        *reinterpret_cast<uint2*>(smc + SM_QH + off) = hi;
        *reinterpret_cast<uint2*>(smc + SM_QL + off) = lo;
    }

    float Oa[32];
    float l0 = 0.0f, l1 = 0.0f;
#pragma unroll
    for (int i = 0; i < 32; i++) Oa[i] = 0.0f;

    const int nkt = (qt == 0) ? (SS / BN) : (qt + 1);
    const int qg0 = q0 + wid * 16 + (lane >> 2);
    const int qg1 = qg0 + 8;

    for (int kt = 0; kt < nkt; kt++) {
        const int k0 = kt * BN;
        __syncthreads();

#pragma unroll
        for (int it = 0; it < 8; it++) {
            int idx = it * 128 + tid;
            int r = idx >> 4;
            int g = idx & 15;
            uint32_t off = swz((uint32_t)(r * 128 + g * 8));
            float4 k4 = *reinterpret_cast<const float4*>(Kb + (size_t)(k0 + r) * DD + g * 4);
            uint2 hi, lo;
            split4(k4, hi, lo);
            *reinterpret_cast<uint2*>(smc + SM_KH + off) = hi;
            *reinterpret_cast<uint2*>(smc + SM_KL + off) = lo;
            float4 v4 = *reinterpret_cast<const float4*>(Vb + (size_t)(k0 + r) * DD + g * 4);
            split4(v4, hi, lo);
            *reinterpret_cast<uint2*>(smc + SM_VH + off) = hi;
            *reinterpret_cast<uint2*>(smc + SM_VL + off) = lo;
        }
        __syncthreads();

        float sc[32];
#pragma unroll
        for (int i = 0; i < 32; i++) sc[i] = 0.0f;

#pragma unroll
        for (int kc = 0; kc < 4; kc++) {
            uint32_t ah[4], al[4];
            uint32_t offA = swz((uint32_t)((wid * 16 + (lane & 15)) * 128 +
                                           (kc * 16 + (lane >> 4) * 8) * 2));
            ldsm4(ah, sb + SM_QH + offA);
            ldsm4(al, sb + SM_QL + offA);
#pragma unroll
            for (int nt4 = 0; nt4 < 4; nt4++) {
                uint32_t offB = swz((uint32_t)((nt4 * 16 + (lane & 7) + ((lane >> 4) << 3)) * 128 +
                                               (kc * 16 + ((lane >> 3) & 1) * 8) * 2));
                uint32_t bh[4], bl[4];
                ldsm4(bh, sb + SM_KH + offB);
                ldsm4(bl, sb + SM_KL + offB);
                float* c0 = &sc[nt4 * 8];
                float* c1 = &sc[nt4 * 8 + 4];
                mma16816(c0, ah, bh[0], bh[1]);
                mma16816(c1, ah, bh[2], bh[3]);
                mma16816(c0, al, bh[0], bh[1]);
                mma16816(c1, al, bh[2], bh[3]);
                mma16816(c0, ah, bl[0], bl[1]);
                mma16816(c1, ah, bl[2], bl[3]);
            }
        }

        uint32_t ph[16], pl[16];
#pragma unroll
        for (int nt = 0; nt < 8; nt++) {
            const int kg = k0 + nt * 8 + 2 * (lane & 3);
            float p0 = (kg     >= qg0) ? EPS_MASKED : __expf(sc[nt * 4 + 0] * 0.125f);
            float p1 = (kg + 1 >= qg0) ? EPS_MASKED : __expf(sc[nt * 4 + 1] * 0.125f);
            float p2 = (kg     >= qg1) ? EPS_MASKED : __expf(sc[nt * 4 + 2] * 0.125f);
            float p3 = (kg + 1 >= qg1) ? EPS_MASKED : __expf(sc[nt * 4 + 3] * 0.125f);
            l0 += p0 + p1;
            l1 += p2 + p3;
            split2(p0, p1, ph[nt * 2 + 0], pl[nt * 2 + 0]);
            split2(p2, p3, ph[nt * 2 + 1], pl[nt * 2 + 1]);
        }

#pragma unroll
        for (int c = 0; c < 4; c++) {
            const uint32_t* aH = &ph[c * 4];
            const uint32_t* aL = &pl[c * 4];
#pragma unroll
            for (int d4 = 0; d4 < 4; d4++) {
                uint32_t offV = swz((uint32_t)((c * 16 + (lane & 7) + ((lane >> 3) & 1) * 8) * 128 +
                                               (d4 * 16 + (lane >> 4) * 8) * 2));
                uint32_t bh[4], bl[4];
                ldsm4t(bh, sb + SM_VH + offV);
                ldsm4t(bl, sb + SM_VL + offV);
                float* o0 = &Oa[d4 * 8];
                float* o1 = &Oa[d4 * 8 + 4];
                mma16816(o0, aH, bh[0], bh[1]);
                mma16816(o1, aH, bh[2], bh[3]);
                mma16816(o0, aL, bh[0], bh[1]);
                mma16816(o1, aL, bh[2], bh[3]);
                mma16816(o0, aH, bl[0], bl[1]);
                mma16816(o1, aH, bl[2], bl[3]);
            }
        }
    }

    // ---- Epilogue: reduce l across quad, normalize, split-write ctx hi/lo ----
    l0 += __shfl_xor_sync(0xffffffffu, l0, 1);
    l0 += __shfl_xor_sync(0xffffffffu, l0, 2);
    l1 += __shfl_xor_sync(0xffffffffu, l1, 1);
    l1 += __shfl_xor_sync(0xffffffffu, l1, 2);
    const float inv0 = 1.0f / l0;
    const float inv1 = 1.0f / l1;

    const int row0 = q0 + wid * 16 + (lane >> 2);
    const size_t base0 = ((size_t)(b * SS + row0)) * DD + h * DQ;
    const size_t base1 = base0 + (size_t)8 * DD;
#pragma unroll
    for (int nt = 0; nt < 8; nt++) {
        const int col = nt * 8 + 2 * (lane & 3);
        uint32_t hi, lo;
        split2(Oa[nt * 4 + 0] * inv0, Oa[nt * 4 + 1] * inv0, hi, lo);
        *reinterpret_cast<uint32_t*>(&g_ctx_h[base0 + col]) = hi;
        *reinterpret_cast<uint32_t*>(&g_ctx_l[base0 + col]) = lo;
        split2(Oa[nt * 4 + 2] * inv1, Oa[nt * 4 + 3] * inv1, hi, lo);
        *reinterpret_cast<uint32_t*>(&g_ctx_h[base1 + col]) = hi;
        *reinterpret_cast<uint32_t*>(&g_ctx_l[base1 + col]) = lo;
    }
}

// ===========================================================================
// Projection via mma.sync: out[4096,1024] = ctx @ W^T + b.
// 128 threads (4 warps x 16 rows), 64x64 CTA tile, BK=64. Grid (16, 64).
// Inputs already split bf16 (g_ctx_h/l, g_w_h/l) -> hot loop is copy+mma only.
// ===========================================================================
extern "C" __global__ void __launch_bounds__(128)
proj_mma(const float* __restrict__ bias,
         float* __restrict__ out)
{
    __shared__ __align__(16) char sA[16384];   // Ah | Al (8 KB each)
    __shared__ __align__(16) char sB[16384];   // Bh | Bl
    const uint32_t sa = smem_u32(sA);
    const uint32_t sbm = smem_u32(sB);

    const int tid  = threadIdx.x;
    const int lane = tid & 31;
    const int wid  = tid >> 5;
    const int j0   = blockIdx.x * 64;   // out cols (W rows)
    const int i0   = blockIdx.y * 64;   // out rows (ctx rows)

    float acc[32];
#pragma unroll
    for (int i = 0; i < 32; i++) acc[i] = 0.0f;

    for (int k0 = 0; k0 < DD; k0 += 64) {
        __syncthreads();
        // Load A (ctx) and B (W) tiles: 64 rows x 64 bf16, hi+lo, swizzled.
#pragma unroll
        for (int it = 0; it < 4; it++) {
            int idx = it * 128 + tid;
            int r = idx >> 3;          // row 0..63
            int g = idx & 7;           // uint4 group (8 bf16)
            uint32_t off = swz((uint32_t)(r * 128 + g * 16));
            size_t aoff = (size_t)(i0 + r) * DD + k0 + g * 8;
            *reinterpret_cast<uint4*>(sA + off)        = *reinterpret_cast<const uint4*>(&g_ctx_h[aoff]);
            *reinterpret_cast<uint4*>(sA + 8192 + off) = *reinterpret_cast<const uint4*>(&g_ctx_l[aoff]);
            size_t boff = (size_t)(j0 + r) * DD + k0 + g * 8;
            *reinterpret_cast<uint4*>(sB + off)        = *reinterpret_cast<const uint4*>(&g_w_h[boff]);
            *reinterpret_cast<uint4*>(sB + 8192 + off) = *reinterpret_cast<const uint4*>(&g_w_l[boff]);
        }
        __syncthreads();

#pragma unroll
        for (int kc = 0; kc < 4; kc++) {
            uint32_t ah[4], al[4];
            uint32_t offA = swz((uint32_t)((wid * 16 + (lane & 15)) * 128 +
                                           (kc * 16 + (lane >> 4) * 8) * 2));
            ldsm4(ah, sa + offA);
            ldsm4(al, sa + 8192 + offA);
#pragma unroll
            for (int nt4 = 0; nt4 < 4; nt4++) {
                uint32_t offB = swz((uint32_t)((nt4 * 16 + (lane & 7) + ((lane >> 4) << 3)) * 128 +
                                               (kc * 16 + ((lane >> 3) & 1) * 8) * 2));
                uint32_t bh[4], bl[4];
                ldsm4(bh, sbm + offB);
                ldsm4(bl, sbm + 8192 + offB);
                float* c0 = &acc[nt4 * 8];
                float* c1 = &acc[nt4 * 8 + 4];
                mma16816(c0, ah, bh[0], bh[1]);   // hi*hi
                mma16816(c1, ah, bh[2], bh[3]);
                mma16816(c0, al, bh[0], bh[1]);   // lo*hi
                mma16816(c1, al, bh[2], bh[3]);
                mma16816(c0, ah, bl[0], bl[1]);   // hi*lo
                mma16816(c1, ah, bl[2], bl[3]);
            }
        }
    }

    // ---- Epilogue: + bias, write f32 ----
    const int row0 = i0 + wid * 16 + (lane >> 2);
    float* d0 = out + (size_t)row0 * DD + j0;
    float* d1 = d0 + (size_t)8 * DD;
#pragma unroll
    for (int nt = 0; nt < 8; nt++) {
        const int col = nt * 8 + 2 * (lane & 3);
        const float b0 = bias[j0 + col];
        const float b1 = bias[j0 + col + 1];
        *reinterpret_cast<float2*>(d0 + col) = make_float2(acc[nt * 4 + 0] + b0, acc[nt * 4 + 1] + b1);
        *reinterpret_cast<float2*>(d1 + col) = make_float2(acc[nt * 4 + 2] + b0, acc[nt * 4 + 3] + b1);
    }
}

// ===========================================================================
extern "C" void kernel_launch(void* const* d_in, const int* in_sizes, int n_in,
                              void* d_out, int out_size)
{
    const float* Q    = (const float*)d_in[0];
    const float* K    = (const float*)d_in[1];
    const float* V    = (const float*)d_in[2];
    const float* Wo_w = (const float*)d_in[3];
    const float* Wo_b = (const float*)d_in[4];

    convert_w<<<(DD * DD / 4) / 256, 256>>>(Wo_w);

    cudaFuncSetAttribute(attn_mma, cudaFuncAttributeMaxDynamicSharedMemorySize, SMEM_BYTES);
    dim3 agrid(SS / BM, HH, BB);          // (32, 16, 2)
    attn_mma<<<agrid, 128, SMEM_BYTES>>>(Q, K, V);

    dim3 pgrid(DD / 64, (BB * SS) / 64);  // (16, 64)
    proj_mma<<<pgrid, 128>>>(Wo_b, (float*)d_out);
}

// round 5
// speedup vs baseline: 1.5228x; 1.5228x over previous
#include <cuda_runtime.h>
#include <cuda_bf16.h>
#include <math.h>
#include <stdint.h>

// Problem constants
#define BB 2
#define SS 2048
#define DD 1024
#define HH 16
#define DQ 64

// Attention tiling
#define BM 64
#define BN 64

#define EPS_MASKED 9.357623e-14f   // exp(-30)

// ctx scratch, split bf16 hi/lo
__device__ __nv_bfloat16 g_ctx_h[BB * SS * DD];
__device__ __nv_bfloat16 g_ctx_l[BB * SS * DD];
// W split bf16 hi/lo
__device__ __nv_bfloat16 g_w_h[DD * DD];
__device__ __nv_bfloat16 g_w_l[DD * DD];

// ===========================================================================
// Helpers
// ===========================================================================
__device__ __forceinline__ uint32_t smem_u32(const void* p) {
    uint32_t a;
    asm("{ .reg .u64 t; cvta.to.shared.u64 t, %1; cvt.u32.u64 %0, t; }" : "=r"(a) : "l"(p));
    return a;
}
__device__ __forceinline__ uint32_t swz(uint32_t off) {
    return off ^ ((off >> 3) & 0x70);
}
__device__ __forceinline__ void ldsm4(uint32_t* r, uint32_t addr) {
    asm volatile("ldmatrix.sync.aligned.m8n8.x4.shared.b16 {%0,%1,%2,%3}, [%4];"
                 : "=r"(r[0]), "=r"(r[1]), "=r"(r[2]), "=r"(r[3]) : "r"(addr));
}
__device__ __forceinline__ void ldsm4t(uint32_t* r, uint32_t addr) {
    asm volatile("ldmatrix.sync.aligned.m8n8.x4.trans.shared.b16 {%0,%1,%2,%3}, [%4];"
                 : "=r"(r[0]), "=r"(r[1]), "=r"(r[2]), "=r"(r[3]) : "r"(addr));
}
__device__ __forceinline__ void mma16816(float* c, const uint32_t* a, uint32_t b0, uint32_t b1) {
    asm volatile("mma.sync.aligned.m16n8k16.row.col.f32.bf16.bf16.f32 "
                 "{%0,%1,%2,%3}, {%4,%5,%6,%7}, {%8,%9}, {%0,%1,%2,%3};"
                 : "+f"(c[0]), "+f"(c[1]), "+f"(c[2]), "+f"(c[3])
                 : "r"(a[0]), "r"(a[1]), "r"(a[2]), "r"(a[3]), "r"(b0), "r"(b1));
}
__device__ __forceinline__ void split2(float x, float y, uint32_t& hi, uint32_t& lo) {
    __nv_bfloat162 h = __floats2bfloat162_rn(x, y);
    float rx = x - __bfloat162float(h.x);
    float ry = y - __bfloat162float(h.y);
    __nv_bfloat162 l = __floats2bfloat162_rn(rx, ry);
    hi = *reinterpret_cast<uint32_t*>(&h);
    lo = *reinterpret_cast<uint32_t*>(&l);
}
__device__ __forceinline__ void split4(float4 v, uint2& hi, uint2& lo) {
    split2(v.x, v.y, hi.x, lo.x);
    split2(v.z, v.w, hi.y, lo.y);
}
__device__ __forceinline__ void cpa16(uint32_t d, const void* s) {
    asm volatile("cp.async.cg.shared.global [%0], [%1], 16;" :: "r"(d), "l"(s));
}
#define CP_COMMIT() asm volatile("cp.async.commit_group;" ::: "memory")
#define CP_WAIT1()  asm volatile("cp.async.wait_group 1;" ::: "memory")

// ===========================================================================
// W pre-split: f32 -> bf16 hi/lo.
// ===========================================================================
extern "C" __global__ void __launch_bounds__(256)
convert_w(const float* __restrict__ W)
{
    int i = blockIdx.x * 256 + threadIdx.x;
    float4 v = reinterpret_cast<const float4*>(W)[i];
    uint2 hi, lo;
    split4(v, hi, lo);
    reinterpret_cast<uint2*>(g_w_h)[i] = hi;
    reinterpret_cast<uint2*>(g_w_l)[i] = lo;
}

// ===========================================================================
// Attention smem layout (unchanged, proven)
// ===========================================================================
#define SM_QH 0
#define SM_QL 8192
#define SM_KH 16384
#define SM_KL 24576
#define SM_VH 32768
#define SM_VL 40960
#define SMEM_BYTES 49152

// ===========================================================================
// Flash attention via mma.sync bf16, 3-term hi/lo split. (unchanged from R4)
// ===========================================================================
extern "C" __global__ void __launch_bounds__(128)
attn_mma(const float* __restrict__ Q,
         const float* __restrict__ K,
         const float* __restrict__ V)
{
    extern __shared__ char smc[];
    const uint32_t sb = smem_u32(smc);
    const int tid  = threadIdx.x;
    const int lane = tid & 31;
    const int wid  = tid >> 5;

    const int bx = blockIdx.x;
    const int qt = (bx == 0) ? 31 : (bx == 1) ? 0 : (32 - bx);
    const int h  = blockIdx.y;
    const int b  = blockIdx.z;
    const int q0 = qt * BM;

    const float* Qb = Q + ((size_t)(b * SS + q0)) * DD + h * DQ;
    const float* Kb = K + ((size_t)b * SS) * DD + h * DQ;
    const float* Vb = V + ((size_t)b * SS) * DD + h * DQ;

#pragma unroll
    for (int it = 0; it < 8; it++) {
        int idx = it * 128 + tid;
        int r = idx >> 4;
        int g = idx & 15;
        float4 q4 = *reinterpret_cast<const float4*>(Qb + (size_t)r * DD + g * 4);
        uint2 hi, lo;
        split4(q4, hi, lo);
        uint32_t off = swz((uint32_t)(r * 128 + g * 8));
        *reinterpret_cast<uint2*>(smc + SM_QH + off) = hi;
        *reinterpret_cast<uint2*>(smc + SM_QL + off) = lo;
    }

    float Oa[32];
    float l0 = 0.0f, l1 = 0.0f;
#pragma unroll
    for (int i = 0; i < 32; i++) Oa[i] = 0.0f;

    const int nkt = (qt == 0) ? (SS / BN) : (qt + 1);
    const int qg0 = q0 + wid * 16 + (lane >> 2);
    const int qg1 = qg0 + 8;

    for (int kt = 0; kt < nkt; kt++) {
        const int k0 = kt * BN;
        __syncthreads();

#pragma unroll
        for (int it = 0; it < 8; it++) {
            int idx = it * 128 + tid;
            int r = idx >> 4;
            int g = idx & 15;
            uint32_t off = swz((uint32_t)(r * 128 + g * 8));
            float4 k4 = *reinterpret_cast<const float4*>(Kb + (size_t)(k0 + r) * DD + g * 4);
            uint2 hi, lo;
            split4(k4, hi, lo);
            *reinterpret_cast<uint2*>(smc + SM_KH + off) = hi;
            *reinterpret_cast<uint2*>(smc + SM_KL + off) = lo;
            float4 v4 = *reinterpret_cast<const float4*>(Vb + (size_t)(k0 + r) * DD + g * 4);
            split4(v4, hi, lo);
            *reinterpret_cast<uint2*>(smc + SM_VH + off) = hi;
            *reinterpret_cast<uint2*>(smc + SM_VL + off) = lo;
        }
        __syncthreads();

        float sc[32];
#pragma unroll
        for (int i = 0; i < 32; i++) sc[i] = 0.0f;

#pragma unroll
        for (int kc = 0; kc < 4; kc++) {
            uint32_t ah[4], al[4];
            uint32_t offA = swz((uint32_t)((wid * 16 + (lane & 15)) * 128 +
                                           (kc * 16 + (lane >> 4) * 8) * 2));
            ldsm4(ah, sb + SM_QH + offA);
            ldsm4(al, sb + SM_QL + offA);
#pragma unroll
            for (int nt4 = 0; nt4 < 4; nt4++) {
                uint32_t offB = swz((uint32_t)((nt4 * 16 + (lane & 7) + ((lane >> 4) << 3)) * 128 +
                                               (kc * 16 + ((lane >> 3) & 1) * 8) * 2));
                uint32_t bh[4], bl[4];
                ldsm4(bh, sb + SM_KH + offB);
                ldsm4(bl, sb + SM_KL + offB);
                float* c0 = &sc[nt4 * 8];
                float* c1 = &sc[nt4 * 8 + 4];
                mma16816(c0, ah, bh[0], bh[1]);
                mma16816(c1, ah, bh[2], bh[3]);
                mma16816(c0, al, bh[0], bh[1]);
                mma16816(c1, al, bh[2], bh[3]);
                mma16816(c0, ah, bl[0], bl[1]);
                mma16816(c1, ah, bl[2], bl[3]);
            }
        }

        uint32_t ph[16], pl[16];
#pragma unroll
        for (int nt = 0; nt < 8; nt++) {
            const int kg = k0 + nt * 8 + 2 * (lane & 3);
            float p0 = (kg     >= qg0) ? EPS_MASKED : __expf(sc[nt * 4 + 0] * 0.125f);
            float p1 = (kg + 1 >= qg0) ? EPS_MASKED : __expf(sc[nt * 4 + 1] * 0.125f);
            float p2 = (kg     >= qg1) ? EPS_MASKED : __expf(sc[nt * 4 + 2] * 0.125f);
            float p3 = (kg + 1 >= qg1) ? EPS_MASKED : __expf(sc[nt * 4 + 3] * 0.125f);
            l0 += p0 + p1;
            l1 += p2 + p3;
            split2(p0, p1, ph[nt * 2 + 0], pl[nt * 2 + 0]);
            split2(p2, p3, ph[nt * 2 + 1], pl[nt * 2 + 1]);
        }

#pragma unroll
        for (int c = 0; c < 4; c++) {
            const uint32_t* aH = &ph[c * 4];
            const uint32_t* aL = &pl[c * 4];
#pragma unroll
            for (int d4 = 0; d4 < 4; d4++) {
                uint32_t offV = swz((uint32_t)((c * 16 + (lane & 7) + ((lane >> 3) & 1) * 8) * 128 +
                                               (d4 * 16 + (lane >> 4) * 8) * 2));
                uint32_t bh[4], bl[4];
                ldsm4t(bh, sb + SM_VH + offV);
                ldsm4t(bl, sb + SM_VL + offV);
                float* o0 = &Oa[d4 * 8];
                float* o1 = &Oa[d4 * 8 + 4];
                mma16816(o0, aH, bh[0], bh[1]);
                mma16816(o1, aH, bh[2], bh[3]);
                mma16816(o0, aL, bh[0], bh[1]);
                mma16816(o1, aL, bh[2], bh[3]);
                mma16816(o0, aH, bl[0], bl[1]);
                mma16816(o1, aH, bl[2], bl[3]);
            }
        }
    }

    l0 += __shfl_xor_sync(0xffffffffu, l0, 1);
    l0 += __shfl_xor_sync(0xffffffffu, l0, 2);
    l1 += __shfl_xor_sync(0xffffffffu, l1, 1);
    l1 += __shfl_xor_sync(0xffffffffu, l1, 2);
    const float inv0 = 1.0f / l0;
    const float inv1 = 1.0f / l1;

    const int row0 = q0 + wid * 16 + (lane >> 2);
    const size_t base0 = ((size_t)(b * SS + row0)) * DD + h * DQ;
    const size_t base1 = base0 + (size_t)8 * DD;
#pragma unroll
    for (int nt = 0; nt < 8; nt++) {
        const int col = nt * 8 + 2 * (lane & 3);
        uint32_t hi, lo;
        split2(Oa[nt * 4 + 0] * inv0, Oa[nt * 4 + 1] * inv0, hi, lo);
        *reinterpret_cast<uint32_t*>(&g_ctx_h[base0 + col]) = hi;
        *reinterpret_cast<uint32_t*>(&g_ctx_l[base0 + col]) = lo;
        split2(Oa[nt * 4 + 2] * inv1, Oa[nt * 4 + 3] * inv1, hi, lo);
        *reinterpret_cast<uint32_t*>(&g_ctx_h[base1 + col]) = hi;
        *reinterpret_cast<uint32_t*>(&g_ctx_l[base1 + col]) = lo;
    }
}

// ===========================================================================
// Projection v2: out[4096,1024] = ctx @ W^T + b via pipelined bf16 GEMM.
// CTA tile 128(M)x64(N), BK=32, 256 threads (8 warps, warp tile 32x32),
// cp.async 2-stage double buffer. Smem rows: [32 h bf16 | 32 l bf16] = 128 B.
// Grid (16, 32).
// ===========================================================================
#define PNIT (DD / 32)   // 32 k-iterations

extern "C" __global__ void __launch_bounds__(256, 2)
proj_mma2(const float* __restrict__ bias,
          float* __restrict__ out)
{
    __shared__ __align__(16) char sA[2][16384];   // 128 rows x 128 B
    __shared__ __align__(16) char sB[2][8192];    // 64 rows x 128 B

    const int tid  = threadIdx.x;
    const int lane = tid & 31;
    const int wid  = tid >> 5;
    const int wm   = wid >> 1;          // 0..3 (M)
    const int wn   = wid & 1;           // 0..1 (N)
    const int j0   = blockIdx.x * 64;   // out col block
    const int i0   = blockIdx.y * 128;  // out row block

    const uint32_t sa0 = smem_u32(sA[0]);
    const uint32_t sa1 = smem_u32(sA[1]);
    const uint32_t sb0 = smem_u32(sB[0]);
    const uint32_t sb1 = smem_u32(sB[1]);

    float acc[32];
#pragma unroll
    for (int i = 0; i < 32; i++) acc[i] = 0.0f;

    // ---- async load of one stage ----
    auto issue = [&](int stage, int k0) {
        const uint32_t sa = stage ? sa1 : sa0;
        const uint32_t sbm = stage ? sb1 : sb0;
#pragma unroll
        for (int q = 0; q < 4; q++) {           // A: 1024 16-B chunks
            int id = q * 256 + tid;
            int r = id >> 3;
            int g = id & 7;
            const __nv_bfloat16* src = (g < 4)
                ? &g_ctx_h[(size_t)(i0 + r) * DD + k0 + g * 8]
                : &g_ctx_l[(size_t)(i0 + r) * DD + k0 + (g - 4) * 8];
            cpa16(sa + swz((uint32_t)(r * 128 + g * 16)), src);
        }
#pragma unroll
        for (int q = 0; q < 2; q++) {           // B: 512 16-B chunks
            int id = q * 256 + tid;
            int r = id >> 3;
            int g = id & 7;
            const __nv_bfloat16* src = (g < 4)
                ? &g_w_h[(size_t)(j0 + r) * DD + k0 + g * 8]
                : &g_w_l[(size_t)(j0 + r) * DD + k0 + (g - 4) * 8];
            cpa16(sbm + swz((uint32_t)(r * 128 + g * 16)), src);
        }
    };

    issue(0, 0);  CP_COMMIT();
    issue(1, 32); CP_COMMIT();

    for (int it = 0; it < PNIT; it++) {
        CP_WAIT1();
        __syncthreads();
        const uint32_t sa = (it & 1) ? sa1 : sa0;
        const uint32_t sbm = (it & 1) ? sb1 : sb0;

#pragma unroll
        for (int kc = 0; kc < 2; kc++) {
            const int kk = kc * 16;
            uint32_t ah[2][4], al[2][4];
#pragma unroll
            for (int m = 0; m < 2; m++) {
                const uint32_t row = wm * 32 + m * 16 + (lane & 15);
                const uint32_t colb = (kk + (lane >> 4) * 8) * 2;
                ldsm4(ah[m], sa + swz(row * 128 + colb));
                ldsm4(al[m], sa + swz(row * 128 + 64 + colb));
            }
            uint32_t bh[2][4], bl[2][4];
#pragma unroll
            for (int nt = 0; nt < 2; nt++) {
                const uint32_t rowb = wn * 32 + nt * 16 + (lane & 7) + ((lane >> 4) << 3);
                const uint32_t colb = (kk + ((lane >> 3) & 1) * 8) * 2;
                ldsm4(bh[nt], sbm + swz(rowb * 128 + colb));
                ldsm4(bl[nt], sbm + swz(rowb * 128 + 64 + colb));
            }
#pragma unroll
            for (int m = 0; m < 2; m++)
#pragma unroll
                for (int nt = 0; nt < 2; nt++) {
                    float* c0 = &acc[(m * 2 + nt) * 8];
                    float* c1 = c0 + 4;
                    mma16816(c0, ah[m], bh[nt][0], bh[nt][1]);   // hi*hi
                    mma16816(c1, ah[m], bh[nt][2], bh[nt][3]);
                    mma16816(c0, al[m], bh[nt][0], bh[nt][1]);   // lo*hi
                    mma16816(c1, al[m], bh[nt][2], bh[nt][3]);
                    mma16816(c0, ah[m], bl[nt][0], bl[nt][1]);   // hi*lo
                    mma16816(c1, ah[m], bl[nt][2], bl[nt][3]);
                }
        }

        __syncthreads();
        if (it + 2 < PNIT) {
            issue(it & 1, (it + 2) * 32);
        }
        CP_COMMIT();
    }

    // ---- Epilogue: + bias, f32 out ----
#pragma unroll
    for (int m = 0; m < 2; m++) {
        const int row = i0 + wm * 32 + m * 16 + (lane >> 2);
        float* d0 = out + (size_t)row * DD;
        float* d1 = d0 + (size_t)8 * DD;
#pragma unroll
        for (int nt = 0; nt < 2; nt++) {
#pragma unroll
            for (int n8 = 0; n8 < 2; n8++) {
                const int col = j0 + wn * 32 + nt * 16 + n8 * 8 + 2 * (lane & 3);
                const float* c = &acc[(m * 2 + nt) * 8 + n8 * 4];
                const float b0 = bias[col];
                const float b1 = bias[col + 1];
                *reinterpret_cast<float2*>(d0 + col) = make_float2(c[0] + b0, c[1] + b1);
                *reinterpret_cast<float2*>(d1 + col) = make_float2(c[2] + b0, c[3] + b1);
            }
        }
    }
}

// ===========================================================================
extern "C" void kernel_launch(void* const* d_in, const int* in_sizes, int n_in,
                              void* d_out, int out_size)
{
    const float* Q    = (const float*)d_in[0];
    const float* K    = (const float*)d_in[1];
    const float* V    = (const float*)d_in[2];
    const float* Wo_w = (const float*)d_in[3];
    const float* Wo_b = (const float*)d_in[4];

    convert_w<<<(DD * DD / 4) / 256, 256>>>(Wo_w);

    cudaFuncSetAttribute(attn_mma, cudaFuncAttributeMaxDynamicSharedMemorySize, SMEM_BYTES);
    dim3 agrid(SS / BM, HH, BB);          // (32, 16, 2)
    attn_mma<<<agrid, 128, SMEM_BYTES>>>(Q, K, V);

    dim3 pgrid(DD / 64, (BB * SS) / 128); // (16, 32)
    proj_mma2<<<pgrid, 256>>>(Wo_b, (float*)d_out);
}